// round 1
// baseline (speedup 1.0000x reference)
#include <cuda_runtime.h>
#include <math.h>

// Problem constants (fixed by the reference)
#define NROWS 8192
#define DIM   256
__device__ __constant__ float c_dummy; // keep compiler honest
constexpr float INV_TEMP = 1.0f / 0.07f;

// Scratch (no cudaMalloc allowed) — device globals.
__device__ float g_rowsum[NROWS];
__device__ float g_diag[NROWS];

// ---------------------------------------------------------------------------
// Kernel 0: zero the row-sum accumulator (d_out/scratch are poisoned per run)
// ---------------------------------------------------------------------------
__global__ void zero_kernel() {
    int i = blockIdx.x * blockDim.x + threadIdx.x;
    if (i < NROWS) g_rowsum[i] = 0.0f;
}

// ---------------------------------------------------------------------------
// Kernel 1: diagonal dots d_i = x_i . y_i  (exact fp32, one warp per row)
// ---------------------------------------------------------------------------
__global__ __launch_bounds__(256) void diag_kernel(const float* __restrict__ X,
                                                   const float* __restrict__ Y) {
    int warp = threadIdx.x >> 5;
    int lane = threadIdx.x & 31;
    int row  = blockIdx.x * 8 + warp;
    if (row >= NROWS) return;
    const float4* xr = reinterpret_cast<const float4*>(X + (size_t)row * DIM);
    const float4* yr = reinterpret_cast<const float4*>(Y + (size_t)row * DIM);
    float s = 0.0f;
    #pragma unroll
    for (int k = lane; k < DIM / 4; k += 32) {
        float4 a = xr[k];
        float4 b = yr[k];
        s += a.x * b.x + a.y * b.y + a.z * b.z + a.w * b.w;
    }
    #pragma unroll
    for (int o = 16; o > 0; o >>= 1) s += __shfl_xor_sync(0xFFFFFFFFu, s, o);
    if (lane == 0) g_diag[row] = s;
}

// ---------------------------------------------------------------------------
// Kernel 2: tiled sim-GEMM + exp + row-sum epilogue.
// Each block: 128 rows (x) x 128 cols (y), full K=256.
// Register tile 8x8 per thread, 256 threads (16x16), BK=16 smem staging.
// ---------------------------------------------------------------------------
#define BM 128
#define BN 128
#define BK 16
#define TM 8
#define TN 8

__global__ __launch_bounds__(256) void simsum_kernel(const float* __restrict__ X,
                                                     const float* __restrict__ Y) {
    __shared__ float As[BK][BM];       // x tile, transposed: As[k][row]
    __shared__ float Bs[BK][BN];       // y tile, transposed: Bs[k][col]
    __shared__ float red[BM][16];      // per-row partial reduction across tx

    const int row0 = blockIdx.y * BM;
    const int col0 = blockIdx.x * BN;
    const int tid  = threadIdx.x;
    const int tx   = tid & 15;         // 0..15 -> column group
    const int ty   = tid >> 4;         // 0..15 -> row group

    float acc[TM][TN];
    #pragma unroll
    for (int i = 0; i < TM; i++)
        #pragma unroll
        for (int j = 0; j < TN; j++) acc[i][j] = 0.0f;

    for (int k0 = 0; k0 < DIM; k0 += BK) {
        // Stage tiles: 128 rows x 16 k = 512 float4 per operand; 2 per thread.
        #pragma unroll
        for (int l = 0; l < 2; l++) {
            int idx = tid + l * 256;       // 0..511
            int r   = idx >> 2;            // tile row/col index 0..127
            int c4  = idx & 3;             // which float4 along k
            float4 a = *reinterpret_cast<const float4*>(
                X + (size_t)(row0 + r) * DIM + k0 + c4 * 4);
            As[c4 * 4 + 0][r] = a.x;
            As[c4 * 4 + 1][r] = a.y;
            As[c4 * 4 + 2][r] = a.z;
            As[c4 * 4 + 3][r] = a.w;
            float4 b = *reinterpret_cast<const float4*>(
                Y + (size_t)(col0 + r) * DIM + k0 + c4 * 4);
            Bs[c4 * 4 + 0][r] = b.x;
            Bs[c4 * 4 + 1][r] = b.y;
            Bs[c4 * 4 + 2][r] = b.z;
            Bs[c4 * 4 + 3][r] = b.w;
        }
        __syncthreads();

        #pragma unroll
        for (int kk = 0; kk < BK; kk++) {
            float ra[TM], rb[TN];
            #pragma unroll
            for (int i = 0; i < TM; i++) ra[i] = As[kk][ty * TM + i];
            #pragma unroll
            for (int j = 0; j < TN; j++) rb[j] = Bs[kk][tx * TN + j];
            #pragma unroll
            for (int i = 0; i < TM; i++)
                #pragma unroll
                for (int j = 0; j < TN; j++)
                    acc[i][j] = fmaf(ra[i], rb[j], acc[i][j]);
        }
        __syncthreads();
    }

    // Epilogue: exp(sim/T) and per-thread row partials
    float rp[TM];
    #pragma unroll
    for (int i = 0; i < TM; i++) {
        float s = 0.0f;
        #pragma unroll
        for (int j = 0; j < TN; j++) s += __expf(acc[i][j] * INV_TEMP);
        rp[i] = s;
    }

    // Reduce across the 16 column-groups (tx) for each row
    #pragma unroll
    for (int i = 0; i < TM; i++) red[ty * TM + i][tx] = rp[i];
    __syncthreads();

    if (tid < BM) {
        float s = 0.0f;
        #pragma unroll
        for (int t = 0; t < 16; t++) s += red[tid][t];
        atomicAdd(&g_rowsum[row0 + tid], s);
    }
}

// ---------------------------------------------------------------------------
// Kernel 3: loss = mean_i [ log(rowsum_i - exp(d_i/T)) - d_i/T ]
// ---------------------------------------------------------------------------
__global__ __launch_bounds__(256) void loss_kernel(float* __restrict__ out) {
    __shared__ double sh[256];
    double s = 0.0;
    for (int i = threadIdx.x; i < NROWS; i += 256) {
        float d    = g_diag[i] * INV_TEMP;
        float lneg = g_rowsum[i] - __expf(d);
        s += (double)(logf(lneg) - d);
    }
    sh[threadIdx.x] = s;
    __syncthreads();
    #pragma unroll
    for (int o = 128; o > 0; o >>= 1) {
        if (threadIdx.x < o) sh[threadIdx.x] += sh[threadIdx.x + o];
        __syncthreads();
    }
    if (threadIdx.x == 0) out[0] = (float)(sh[0] / (double)NROWS);
}

// ---------------------------------------------------------------------------
// Entry point
// ---------------------------------------------------------------------------
extern "C" void kernel_launch(void* const* d_in, const int* in_sizes, int n_in,
                              void* d_out, int out_size) {
    const float* X = (const float*)d_in[0];
    const float* Y = (const float*)d_in[1];
    float* out = (float*)d_out;

    zero_kernel<<<(NROWS + 255) / 256, 256>>>();
    diag_kernel<<<NROWS / 8, 256>>>(X, Y);
    dim3 grid(NROWS / BN, NROWS / BM);
    simsum_kernel<<<grid, 256>>>(X, Y);
    loss_kernel<<<1, 256>>>(out);
}

// round 3
// speedup vs baseline: 7.6046x; 7.6046x over previous
#include <cuda_runtime.h>
#include <cuda_bf16.h>
#include <cstdint>
#include <math.h>

// ---------------------------------------------------------------------------
// Problem constants
// ---------------------------------------------------------------------------
#define NROWS 8192
#define DIM   256
constexpr float INV_TEMP = 1.0f / 0.07f;

// GEMM tiling
#define BM 128
#define BN 128
#define BK 64
#define NKT (DIM / BK)   // 4 k-tiles

// SMEM layout (dynamic): A[2] 16KB each, B[2] 16KB each, red 2KB
#define SM_A(s)   ((s) * 16384)
#define SM_B(s)   (32768 + (s) * 16384)
#define SM_RED    65536
#define SMEM_TOTAL (65536 + 128 * 4 * 4)

// ---------------------------------------------------------------------------
// Scratch (device globals; no allocations allowed)
// ---------------------------------------------------------------------------
__device__ float g_rowsum[NROWS];
__device__ float g_diag[NROWS];
__device__ __nv_bfloat16 g_xb[NROWS * DIM];
__device__ __nv_bfloat16 g_yb[NROWS * DIM];

// ---------------------------------------------------------------------------
// Helpers
// ---------------------------------------------------------------------------
__device__ __forceinline__ uint32_t smem_to_u32(const void* p) {
    uint32_t a;
    asm("{ .reg .u64 t; cvta.to.shared.u64 t, %1; cvt.u32.u64 %0, t; }"
        : "=r"(a) : "l"(p));
    return a;
}

__device__ __forceinline__ void cp16(uint32_t saddr, const void* gaddr) {
    asm volatile("cp.async.cg.shared.global [%0], [%1], 16;"
                 :: "r"(saddr), "l"(gaddr) : "memory");
}
#define CP_COMMIT()  asm volatile("cp.async.commit_group;" ::: "memory")
#define CP_WAIT(n)   asm volatile("cp.async.wait_group %0;" :: "n"(n) : "memory")

#define LDSM4(r0, r1, r2, r3, addr)                                          \
    asm volatile("ldmatrix.sync.aligned.m8n8.x4.shared.b16 {%0,%1,%2,%3}, [%4];" \
                 : "=r"(r0), "=r"(r1), "=r"(r2), "=r"(r3) : "r"(addr))

#define MMA16816(d, a, b0, b1)                                               \
    asm volatile("mma.sync.aligned.m16n8k16.row.col.f32.bf16.bf16.f32 "      \
                 "{%0,%1,%2,%3}, {%4,%5,%6,%7}, {%8,%9}, {%0,%1,%2,%3};"     \
                 : "+f"(d[0]), "+f"(d[1]), "+f"(d[2]), "+f"(d[3])            \
                 : "r"(a[0]), "r"(a[1]), "r"(a[2]), "r"(a[3]),               \
                   "r"(b0), "r"(b1))

// ---------------------------------------------------------------------------
// Kernel: fp32 -> bf16 conversion for both inputs
// ---------------------------------------------------------------------------
__global__ __launch_bounds__(256) void convert_kernel(const float* __restrict__ X,
                                                      const float* __restrict__ Y) {
    const int n = NROWS * DIM / 4;
    int i = blockIdx.x * blockDim.x + threadIdx.x;
    const float4* src;
    __nv_bfloat16* dst;
    int j;
    if (i < n) { src = (const float4*)X; dst = g_xb; j = i; }
    else       { src = (const float4*)Y; dst = g_yb; j = i - n; }
    float4 v = src[j];
    *reinterpret_cast<__nv_bfloat162*>(dst + (size_t)j * 4)     = __floats2bfloat162_rn(v.x, v.y);
    *reinterpret_cast<__nv_bfloat162*>(dst + (size_t)j * 4 + 2) = __floats2bfloat162_rn(v.z, v.w);
}

// ---------------------------------------------------------------------------
// Kernel: zero row sums
// ---------------------------------------------------------------------------
__global__ void zero_kernel() {
    int i = blockIdx.x * blockDim.x + threadIdx.x;
    if (i < NROWS) g_rowsum[i] = 0.0f;
}

// ---------------------------------------------------------------------------
// Kernel: exact fp32 diagonal dots
// ---------------------------------------------------------------------------
__global__ __launch_bounds__(256) void diag_kernel(const float* __restrict__ X,
                                                   const float* __restrict__ Y) {
    int warp = threadIdx.x >> 5, lane = threadIdx.x & 31;
    int row = blockIdx.x * 8 + warp;
    const float4* xr = reinterpret_cast<const float4*>(X + (size_t)row * DIM);
    const float4* yr = reinterpret_cast<const float4*>(Y + (size_t)row * DIM);
    float s = 0.0f;
    #pragma unroll
    for (int k = lane; k < DIM / 4; k += 32) {
        float4 a = xr[k], b = yr[k];
        s += a.x * b.x + a.y * b.y + a.z * b.z + a.w * b.w;
    }
    #pragma unroll
    for (int o = 16; o > 0; o >>= 1) s += __shfl_xor_sync(0xFFFFFFFFu, s, o);
    if (lane == 0) g_diag[row] = s;
}

// ---------------------------------------------------------------------------
// Kernel: HMMA bf16 sim-GEMM + exp + row-sum epilogue
// CTA tile 128x128, 8 warps (2 M x 4 N), warp tile 64x32, cp.async 2-stage.
// ---------------------------------------------------------------------------
__device__ __forceinline__ void stage_load(uint32_t sb, int s, int row0, int col0,
                                           int kt, int tid) {
    const int k0 = kt * BK;
    const uint32_t Ab = sb + SM_A(s);
    const uint32_t Bb = sb + SM_B(s);
    const __nv_bfloat16* Ag = g_xb + (size_t)row0 * DIM + k0;
    const __nv_bfloat16* Bg = g_yb + (size_t)col0 * DIM + k0;
    #pragma unroll
    for (int it = 0; it < 4; it++) {
        int idx = tid + it * 256;          // 0..1023
        int r = idx >> 3, c = idx & 7;
        cp16(Ab + r * 128 + ((c ^ (r & 7)) << 4), Ag + (size_t)r * DIM + c * 8);
    }
    #pragma unroll
    for (int it = 0; it < 4; it++) {
        int idx = tid + it * 256;
        int r = idx >> 3, c = idx & 7;
        cp16(Bb + r * 128 + ((c ^ (r & 7)) << 4), Bg + (size_t)r * DIM + c * 8);
    }
}

__global__ __launch_bounds__(256, 2) void simsum_hmma_kernel() {
    extern __shared__ char smem[];
    const uint32_t sb = smem_to_u32(smem);
    const int tid = threadIdx.x;
    const int wid = tid >> 5, lid = tid & 31;
    const int wm = wid >> 2, wn = wid & 3;        // warp grid 2 (M) x 4 (N)
    const int m_base = wm * 64, n_base = wn * 32;
    const int row0 = blockIdx.y * BM, col0 = blockIdx.x * BN;

    const int sub = lid >> 3, l7 = lid & 7;
    const int a_row_off = ((sub & 1) << 3) + l7;  // row within m16 tile
    const int a_c_off   = sub >> 1;               // k chunk select (0/1)
    const int b_row_off = ((sub >> 1) << 3) + l7; // row within n16 pair
    const int b_c_off   = sub & 1;

    // Prime pipeline
    stage_load(sb, 0, row0, col0, 0, tid);
    CP_COMMIT();

    float acc[4][4][4];
    #pragma unroll
    for (int i = 0; i < 4; i++)
        #pragma unroll
        for (int j = 0; j < 4; j++)
            #pragma unroll
            for (int r = 0; r < 4; r++) acc[i][j][r] = 0.0f;

    #pragma unroll
    for (int t = 0; t < NKT; t++) {
        if (t + 1 < NKT) {
            stage_load(sb, (t + 1) & 1, row0, col0, t + 1, tid);
            CP_COMMIT();
            CP_WAIT(1);
        } else {
            CP_WAIT(0);
        }
        __syncthreads();

        const uint32_t Abase = sb + SM_A(t & 1);
        const uint32_t Bbase = sb + SM_B(t & 1);
        #pragma unroll
        for (int kk = 0; kk < BK / 16; kk++) {
            uint32_t a[4][4];
            #pragma unroll
            for (int mi = 0; mi < 4; mi++) {
                int row = m_base + mi * 16 + a_row_off;
                int c = kk * 2 + a_c_off;
                uint32_t addr = Abase + row * 128 + ((c ^ (row & 7)) << 4);
                LDSM4(a[mi][0], a[mi][1], a[mi][2], a[mi][3], addr);
            }
            uint32_t b[2][4];
            #pragma unroll
            for (int p = 0; p < 2; p++) {
                int nrow = n_base + p * 16 + b_row_off;
                int c = kk * 2 + b_c_off;
                uint32_t addr = Bbase + nrow * 128 + ((c ^ (nrow & 7)) << 4);
                LDSM4(b[p][0], b[p][1], b[p][2], b[p][3], addr);
            }
            #pragma unroll
            for (int mi = 0; mi < 4; mi++)
                #pragma unroll
                for (int ni = 0; ni < 4; ni++)
                    MMA16816(acc[mi][ni], a[mi],
                             b[ni >> 1][(ni & 1) << 1],
                             b[ni >> 1][((ni & 1) << 1) + 1]);
        }
        __syncthreads();
    }

    // Epilogue: exp + row sums.
    // D fragment lane map: g = lid>>2 row in tile (and g+8), t = lid&3 col pair.
    float* red = reinterpret_cast<float*>(smem + SM_RED);  // [128 rows][4 wn]
    const int g = lid >> 2;
    #pragma unroll
    for (int mi = 0; mi < 4; mi++) {
        float lo = 0.0f, hi = 0.0f;
        #pragma unroll
        for (int ni = 0; ni < 4; ni++) {
            lo += __expf(acc[mi][ni][0] * INV_TEMP) + __expf(acc[mi][ni][1] * INV_TEMP);
            hi += __expf(acc[mi][ni][2] * INV_TEMP) + __expf(acc[mi][ni][3] * INV_TEMP);
        }
        lo += __shfl_xor_sync(0xFFFFFFFFu, lo, 1);
        lo += __shfl_xor_sync(0xFFFFFFFFu, lo, 2);
        hi += __shfl_xor_sync(0xFFFFFFFFu, hi, 1);
        hi += __shfl_xor_sync(0xFFFFFFFFu, hi, 2);
        if ((lid & 3) == 0) {
            red[(m_base + mi * 16 + g) * 4 + wn] = lo;
            red[(m_base + mi * 16 + g + 8) * 4 + wn] = hi;
        }
    }
    __syncthreads();
    if (tid < BM) {
        float4 v = reinterpret_cast<float4*>(red)[tid];
        atomicAdd(&g_rowsum[row0 + tid], v.x + v.y + v.z + v.w);
    }
}

// ---------------------------------------------------------------------------
// Kernel: final loss
// ---------------------------------------------------------------------------
__global__ __launch_bounds__(1024) void loss_kernel(float* __restrict__ out) {
    __shared__ double sh[1024];
    double s = 0.0;
    for (int i = threadIdx.x; i < NROWS; i += 1024) {
        float d = g_diag[i] * INV_TEMP;
        float lneg = g_rowsum[i] - __expf(d);
        s += (double)(logf(lneg) - d);
    }
    sh[threadIdx.x] = s;
    __syncthreads();
    #pragma unroll
    for (int o = 512; o > 0; o >>= 1) {
        if (threadIdx.x < o) sh[threadIdx.x] += sh[threadIdx.x + o];
        __syncthreads();
    }
    if (threadIdx.x == 0) out[0] = (float)(sh[0] / (double)NROWS);
}

// ---------------------------------------------------------------------------
// Entry point
// ---------------------------------------------------------------------------
extern "C" void kernel_launch(void* const* d_in, const int* in_sizes, int n_in,
                              void* d_out, int out_size) {
    const float* X = (const float*)d_in[0];
    const float* Y = (const float*)d_in[1];
    float* out = (float*)d_out;

    static bool attr_set = false;
    if (!attr_set) {
        cudaFuncSetAttribute(simsum_hmma_kernel,
                             cudaFuncAttributeMaxDynamicSharedMemorySize, SMEM_TOTAL);
        attr_set = true;
    }

    convert_kernel<<<(2 * NROWS * DIM / 4 + 255) / 256, 256>>>(X, Y);
    zero_kernel<<<NROWS / 256, 256>>>();
    diag_kernel<<<NROWS / 8, 256>>>(X, Y);
    dim3 grid(NROWS / BN, NROWS / BM);   // (64, 64)
    simsum_hmma_kernel<<<grid, 256, SMEM_TOTAL>>>();
    loss_kernel<<<1, 1024>>>(out);
}